// round 12
// baseline (speedup 1.0000x reference)
#include <cuda_runtime.h>

#define SQ 256
#define BQ 256
#define DQ 256
#define HQ 8
#define STR (BQ * 32)   // floats per timestep in d_pre

// scratch: pre-activations, padded by 4 steps so distance-4 prefetch is
// branch-free (pad reads land in registers but are never consumed; the
// array is in-bounds so no trap, output unaffected).
__device__ float d_pre[(SQ + 4) * STR];

__device__ __forceinline__ float htanh(float x) {
    float r;
    asm("tanh.approx.f32 %0, %1;" : "=f"(r) : "f"(x));
    return r;
}

// ---------------------------------------------------------------------------
// Kernel 1: pre[t,b,o] = x[t,b,:] @ Wx[o,:] + bias[o] + theta[o]
// o = g*8+k over 4 gates. M=65536 rows, N=32, K=256.  (R2 scalar version —
// best wall-time evidence.)
// ---------------------------------------------------------------------------
__global__ __launch_bounds__(256) void qlstm_gemm(
    const float* __restrict__ x,
    const float* __restrict__ Wf, const float* __restrict__ bf,
    const float* __restrict__ Wi, const float* __restrict__ bi,
    const float* __restrict__ Wu, const float* __restrict__ bu,
    const float* __restrict__ Wo, const float* __restrict__ bo,
    const float* __restrict__ thf, const float* __restrict__ thi,
    const float* __restrict__ thu, const float* __restrict__ tho)
{
    __shared__ float sW[32][260];   // stride 260: conflict-free LDS.128
    __shared__ float sBias[32];

    int tid = threadIdx.x;

    #pragma unroll 4
    for (int idx = tid; idx < 32 * 256; idx += 256) {
        int o = idx >> 8;
        int d = idx & 255;
        int g = o >> 3, kk = o & 7;
        const float* Wg = (g == 0) ? Wf : (g == 1) ? Wi : (g == 2) ? Wu : Wo;
        sW[o][d] = Wg[kk * 264 + d];
    }
    if (tid < 32) {
        int g = tid >> 3, kk = tid & 7;
        const float* bg = (g == 0) ? bf : (g == 1) ? bi : (g == 2) ? bu : bo;
        const float* tg = (g == 0) ? thf : (g == 1) ? thi : (g == 2) ? thu : tho;
        sBias[tid] = bg[kk] + tg[kk];
    }
    __syncthreads();

    int warp = tid >> 5, lane = tid & 31;
    int o1 = lane & 15, o2 = o1 + 16;
    int rb = blockIdx.x * 128 + warp * 16 + (lane >> 4) * 8;

    float acc0[8], acc1[8];
    #pragma unroll
    for (int r = 0; r < 8; r++) { acc0[r] = 0.f; acc1[r] = 0.f; }

    const float* xp = x + (size_t)rb * 256;

    #pragma unroll 4
    for (int d = 0; d < 256; d += 4) {
        float4 w1 = *reinterpret_cast<const float4*>(&sW[o1][d]);
        float4 w2 = *reinterpret_cast<const float4*>(&sW[o2][d]);
        #pragma unroll
        for (int r = 0; r < 8; r++) {
            float4 xv = *reinterpret_cast<const float4*>(xp + r * 256 + d);
            acc0[r] = fmaf(xv.x, w1.x, acc0[r]);
            acc0[r] = fmaf(xv.y, w1.y, acc0[r]);
            acc0[r] = fmaf(xv.z, w1.z, acc0[r]);
            acc0[r] = fmaf(xv.w, w1.w, acc0[r]);
            acc1[r] = fmaf(xv.x, w2.x, acc1[r]);
            acc1[r] = fmaf(xv.y, w2.y, acc1[r]);
            acc1[r] = fmaf(xv.z, w2.z, acc1[r]);
            acc1[r] = fmaf(xv.w, w2.w, acc1[r]);
        }
    }

    float bb1 = sBias[o1], bb2 = sBias[o2];
    #pragma unroll
    for (int r = 0; r < 8; r++) {
        d_pre[(size_t)(rb + r) * 32 + o1] = acc0[r] + bb1;
        d_pre[(size_t)(rb + r) * 32 + o2] = acc1[r] + bb2;
    }
}

// ---------------------------------------------------------------------------
// Kernel 2: sequential LSTM over 256 steps, one warp per batch row
// (128 blocks x 2 warps — best measured shape). lane = g*8+k.
// R2 body + distance-4 register prefetch pipeline (only change).
// Activations via MUFU.TANH:
//   sigmoid(p) = 0.5 + 0.5*tanh(p/2)  (f,i,o);  tanh(p)  (u)
// ---------------------------------------------------------------------------
__global__ __launch_bounds__(64) void qlstm_recur(
    const float* __restrict__ Wf, const float* __restrict__ Wi,
    const float* __restrict__ Wu, const float* __restrict__ Wo,
    const float* __restrict__ hx, const float* __restrict__ cx,
    float* __restrict__ out)
{
    int w = (blockIdx.x * blockDim.x + threadIdx.x) >> 5;
    int lane = threadIdx.x & 31;
    if (w >= BQ) return;
    int g = lane >> 3, k = lane & 7;

    const float* Wg = (g == 0) ? Wf : (g == 1) ? Wi : (g == 2) ? Wu : Wo;
    float wh[8];
    #pragma unroll
    for (int j = 0; j < 8; j++) wh[j] = Wg[k * 264 + 256 + j];

    // per-lane activation constants (hoisted; branch-free inner loop)
    float M = (g == 2) ? 1.0f : 0.5f;
    float A = (g == 2) ? 1.0f : 0.5f;
    float B = (g == 2) ? 0.0f : 0.5f;

    float h = hx[w * 8 + k];
    float c = cx[w * 8 + k];

    // distance-4 prefetch pipeline (branch-free; d_pre padded by 4 steps)
    const float* pb = d_pre + (size_t)w * 32 + lane;
    float q0 = pb[0 * STR], q1 = pb[1 * STR], q2 = pb[2 * STR], q3 = pb[3 * STR];
    const float* pf = pb + 4 * (size_t)STR;

    float* op = out + (size_t)w * HQ + k;
    const unsigned FULL = 0xffffffffu;

    bool m1p = (k >= 1), m2p = (k >= 2), m3p = (k >= 3), m4p = (k >= 4),
         m5p = (k >= 5), m6p = (k >= 6), m7p = (k >= 7);

#define QSTEP(PQ)                                                            \
    {                                                                        \
        float a0 = (PQ), a1 = 0.f;                                           \
        _Pragma("unroll")                                                    \
        for (int j = 0; j < 8; j += 2) {                                     \
            float hj0 = __shfl_sync(FULL, h, j);                             \
            float hj1 = __shfl_sync(FULL, h, j + 1);                         \
            a0 = fmaf(wh[j], hj0, a0);                                       \
            a1 = fmaf(wh[j + 1], hj1, a1);                                   \
        }                                                                    \
        float ang = a0 + a1;                                                 \
        float cv = __cosf(ang);                                              \
        float c0 = __shfl_sync(FULL, cv, 0, 8);                              \
        float c1 = __shfl_sync(FULL, cv, 1, 8);                              \
        float c2 = __shfl_sync(FULL, cv, 2, 8);                              \
        float c3 = __shfl_sync(FULL, cv, 3, 8);                              \
        float c4 = __shfl_sync(FULL, cv, 4, 8);                              \
        float c5 = __shfl_sync(FULL, cv, 5, 8);                              \
        float c6 = __shfl_sync(FULL, cv, 6, 8);                              \
        float c7 = __shfl_sync(FULL, cv, 7, 8);                              \
        float m1 = m1p ? c1 : 1.f;                                           \
        float m2 = m2p ? c2 : 1.f;                                           \
        float m3 = m3p ? c3 : 1.f;                                           \
        float m4 = m4p ? c4 : 1.f;                                           \
        float m5 = m5p ? c5 : 1.f;                                           \
        float m6 = m6p ? c6 : 1.f;                                           \
        float m7 = m7p ? c7 : 1.f;                                           \
        float p = ((c0 * m1) * (m2 * m3)) * ((m4 * m5) * (m6 * m7));         \
        float act = fmaf(A, htanh(p * M), B);                                \
        float fv = __shfl_sync(FULL, act, k);                                \
        float iv = __shfl_sync(FULL, act, 8 + k);                            \
        float uv = __shfl_sync(FULL, act, 16 + k);                           \
        float ov = __shfl_sync(FULL, act, 24 + k);                           \
        c = fmaf(fv, c, iv * uv);                                            \
        float th = htanh(c);                                                 \
        h = ov * th;                                                         \
        if (g == 0) *op = h;                                                 \
        op += BQ * HQ;                                                       \
    }

    for (int t = 0; t < SQ; t += 2) {
        QSTEP(q0); q0 = q2; q2 = pf[0]; pf += STR;
        QSTEP(q1); q1 = q3; q3 = pf[0]; pf += STR;
    }
#undef QSTEP

    if (g == 0) {
        out[(size_t)SQ * BQ * HQ + (size_t)w * HQ + k] = h;                   // hT
        out[(size_t)SQ * BQ * HQ + (size_t)BQ * HQ + (size_t)w * HQ + k] = c; // cT
    }
}

extern "C" void kernel_launch(void* const* d_in, const int* in_sizes, int n_in,
                              void* d_out, int out_size)
{
    const float* x   = (const float*)d_in[0];
    const float* hx  = (const float*)d_in[1];
    const float* cx  = (const float*)d_in[2];
    const float* Wf  = (const float*)d_in[3];
    const float* bf  = (const float*)d_in[4];
    const float* Wi  = (const float*)d_in[5];
    const float* bi  = (const float*)d_in[6];
    const float* Wu  = (const float*)d_in[7];
    const float* bu  = (const float*)d_in[8];
    const float* Wo  = (const float*)d_in[9];
    const float* bo  = (const float*)d_in[10];
    const float* tf  = (const float*)d_in[11];
    const float* ti  = (const float*)d_in[12];
    const float* tu  = (const float*)d_in[13];
    const float* to_ = (const float*)d_in[14];

    qlstm_gemm<<<512, 256>>>(x, Wf, bf, Wi, bi, Wu, bu, Wo, bo, tf, ti, tu, to_);
    qlstm_recur<<<128, 64>>>(Wf, Wi, Wu, Wo, hx, cx, (float*)d_out);
}

// round 13
// speedup vs baseline: 1.1493x; 1.1493x over previous
#include <cuda_runtime.h>

#define SQ 256
#define BQ 256
#define DQ 256
#define HQ 8

// scratch: pre-activations for all timesteps: pre[t*BQ+b][32]  (8 MB)
__device__ float d_pre[SQ * BQ * 32];

__device__ __forceinline__ float htanh(float x) {
    float r;
    asm("tanh.approx.f32 %0, %1;" : "=f"(r) : "f"(x));
    return r;
}

// ---------------------------------------------------------------------------
// Kernel 1: pre[t,b,o] = x[t,b,:] @ Wx[o,:] + bias[o] + theta[o]
// o = g*8+k over 4 gates. M=65536 rows, N=32, K=256.
// ---------------------------------------------------------------------------
__global__ __launch_bounds__(256) void qlstm_gemm(
    const float* __restrict__ x,
    const float* __restrict__ Wf, const float* __restrict__ bf,
    const float* __restrict__ Wi, const float* __restrict__ bi,
    const float* __restrict__ Wu, const float* __restrict__ bu,
    const float* __restrict__ Wo, const float* __restrict__ bo,
    const float* __restrict__ thf, const float* __restrict__ thi,
    const float* __restrict__ thu, const float* __restrict__ tho)
{
    __shared__ float sW[32][260];   // stride 260: conflict-free LDS.128 across 16 lanes
    __shared__ float sBias[32];

    int tid = threadIdx.x;

    #pragma unroll 4
    for (int idx = tid; idx < 32 * 256; idx += 256) {
        int o = idx >> 8;
        int d = idx & 255;
        int g = o >> 3, kk = o & 7;
        const float* Wg = (g == 0) ? Wf : (g == 1) ? Wi : (g == 2) ? Wu : Wo;
        sW[o][d] = Wg[kk * 264 + d];
    }
    if (tid < 32) {
        int g = tid >> 3, kk = tid & 7;
        const float* bg = (g == 0) ? bf : (g == 1) ? bi : (g == 2) ? bu : bo;
        const float* tg = (g == 0) ? thf : (g == 1) ? thi : (g == 2) ? thu : tho;
        sBias[tid] = bg[kk] + tg[kk];
    }
    __syncthreads();

    int warp = tid >> 5, lane = tid & 31;
    int o1 = lane & 15, o2 = o1 + 16;
    int rb = blockIdx.x * 128 + warp * 16 + (lane >> 4) * 8;

    float acc0[8], acc1[8];
    #pragma unroll
    for (int r = 0; r < 8; r++) { acc0[r] = 0.f; acc1[r] = 0.f; }

    const float* xp = x + (size_t)rb * 256;

    #pragma unroll 4
    for (int d = 0; d < 256; d += 4) {
        float4 w1 = *reinterpret_cast<const float4*>(&sW[o1][d]);
        float4 w2 = *reinterpret_cast<const float4*>(&sW[o2][d]);
        #pragma unroll
        for (int r = 0; r < 8; r++) {
            float4 xv = *reinterpret_cast<const float4*>(xp + r * 256 + d);
            acc0[r] = fmaf(xv.x, w1.x, acc0[r]);
            acc0[r] = fmaf(xv.y, w1.y, acc0[r]);
            acc0[r] = fmaf(xv.z, w1.z, acc0[r]);
            acc0[r] = fmaf(xv.w, w1.w, acc0[r]);
            acc1[r] = fmaf(xv.x, w2.x, acc1[r]);
            acc1[r] = fmaf(xv.y, w2.y, acc1[r]);
            acc1[r] = fmaf(xv.z, w2.z, acc1[r]);
            acc1[r] = fmaf(xv.w, w2.w, acc1[r]);
        }
    }

    float bb1 = sBias[o1], bb2 = sBias[o2];
    #pragma unroll
    for (int r = 0; r < 8; r++) {
        d_pre[(size_t)(rb + r) * 32 + o1] = acc0[r] + bb1;
        d_pre[(size_t)(rb + r) * 32 + o2] = acc1[r] + bb2;
    }
}

// ---------------------------------------------------------------------------
// Kernel 2: sequential LSTM over 256 steps, one warp per batch row.
// lane = g*8+k. qgate(angles)[k] = prod_{j<=k} cos(angles[j]) per gate.
// All activations through MUFU.TANH:
//   sigmoid(p) = 0.5 + 0.5*tanh(p/2)   (gates f,i,o: M=0.5, A=0.5, B=0.5)
//   tanh(p)                            (gate u:      M=1,   A=1,   B=0)
// ---------------------------------------------------------------------------
__global__ __launch_bounds__(64) void qlstm_recur(
    const float* __restrict__ Wf, const float* __restrict__ Wi,
    const float* __restrict__ Wu, const float* __restrict__ Wo,
    const float* __restrict__ hx, const float* __restrict__ cx,
    float* __restrict__ out)
{
    int w = (blockIdx.x * blockDim.x + threadIdx.x) >> 5;
    int lane = threadIdx.x & 31;
    if (w >= BQ) return;
    int g = lane >> 3, k = lane & 7;

    const float* Wg = (g == 0) ? Wf : (g == 1) ? Wi : (g == 2) ? Wu : Wo;
    float wh[8];
    #pragma unroll
    for (int j = 0; j < 8; j++) wh[j] = Wg[k * 264 + 256 + j];

    // per-lane activation constants (hoisted; branch-free inner loop)
    float M = (g == 2) ? 1.0f : 0.5f;
    float A = (g == 2) ? 1.0f : 0.5f;
    float B = (g == 2) ? 0.0f : 0.5f;

    float h = hx[w * 8 + k];
    float c = cx[w * 8 + k];

    const float* pre = d_pre + (size_t)w * 32 + lane;
    float pv = pre[0];
    float pn = pre[(size_t)BQ * 32];
    float* op = out + (size_t)w * HQ + k;
    const unsigned FULL = 0xffffffffu;

    bool m1p = (k >= 1), m2p = (k >= 2), m3p = (k >= 3), m4p = (k >= 4),
         m5p = (k >= 5), m6p = (k >= 6), m7p = (k >= 7);

    for (int t = 0; t < SQ; t++) {
        float pcur = pv;
        pv = pn;
        int tn = (t + 2 < SQ) ? (t + 2) : (SQ - 1);
        pn = pre[(size_t)tn * BQ * 32];

        // recurrent matvec: angle = pre + sum_j Wh[g][k][j] * h_j
        float a0 = pcur, a1 = 0.f;
        #pragma unroll
        for (int j = 0; j < 8; j += 2) {
            float hj0 = __shfl_sync(FULL, h, j);
            float hj1 = __shfl_sync(FULL, h, j + 1);
            a0 = fmaf(wh[j], hj0, a0);
            a1 = fmaf(wh[j + 1], hj1, a1);
        }
        float ang = a0 + a1;

        float cv = __cosf(ang);

        // broadcast this gate's 8 cosines within the 8-lane group (width=8)
        float c0 = __shfl_sync(FULL, cv, 0, 8);
        float c1 = __shfl_sync(FULL, cv, 1, 8);
        float c2 = __shfl_sync(FULL, cv, 2, 8);
        float c3 = __shfl_sync(FULL, cv, 3, 8);
        float c4 = __shfl_sync(FULL, cv, 4, 8);
        float c5 = __shfl_sync(FULL, cv, 5, 8);
        float c6 = __shfl_sync(FULL, cv, 6, 8);
        float c7 = __shfl_sync(FULL, cv, 7, 8);

        // masked prefix product (SEL + mul tree)
        float m1 = m1p ? c1 : 1.f;
        float m2 = m2p ? c2 : 1.f;
        float m3 = m3p ? c3 : 1.f;
        float m4 = m4p ? c4 : 1.f;
        float m5 = m5p ? c5 : 1.f;
        float m6 = m6p ? c6 : 1.f;
        float m7 = m7p ? c7 : 1.f;
        float p = ((c0 * m1) * (m2 * m3)) * ((m4 * m5) * (m6 * m7));

        // unified activation via MUFU.TANH
        float act = fmaf(A, htanh(p * M), B);

        // gather the 4 gate values for my k
        float fv = __shfl_sync(FULL, act, k);
        float iv = __shfl_sync(FULL, act, 8 + k);
        float uv = __shfl_sync(FULL, act, 16 + k);
        float ov = __shfl_sync(FULL, act, 24 + k);

        c = fmaf(fv, c, iv * uv);
        float th = htanh(c);
        h = ov * th;

        if (g == 0) op[(size_t)t * BQ * HQ] = h;
    }

    if (g == 0) {
        out[(size_t)SQ * BQ * HQ + (size_t)w * HQ + k] = h;                   // hT
        out[(size_t)SQ * BQ * HQ + (size_t)BQ * HQ + (size_t)w * HQ + k] = c; // cT
    }
}

extern "C" void kernel_launch(void* const* d_in, const int* in_sizes, int n_in,
                              void* d_out, int out_size)
{
    const float* x   = (const float*)d_in[0];
    const float* hx  = (const float*)d_in[1];
    const float* cx  = (const float*)d_in[2];
    const float* Wf  = (const float*)d_in[3];
    const float* bf  = (const float*)d_in[4];
    const float* Wi  = (const float*)d_in[5];
    const float* bi  = (const float*)d_in[6];
    const float* Wu  = (const float*)d_in[7];
    const float* bu  = (const float*)d_in[8];
    const float* Wo  = (const float*)d_in[9];
    const float* bo  = (const float*)d_in[10];
    const float* tf  = (const float*)d_in[11];
    const float* ti  = (const float*)d_in[12];
    const float* tu  = (const float*)d_in[13];
    const float* to_ = (const float*)d_in[14];

    qlstm_gemm<<<512, 256>>>(x, Wf, bf, Wi, bi, Wu, bu, Wo, bo, tf, ti, tu, to_);
    qlstm_recur<<<128, 64>>>(Wf, Wi, Wu, Wo, hx, cx, (float*)d_out);
}